// round 7
// baseline (speedup 1.0000x reference)
#include <cuda_runtime.h>
#include <math.h>
#include <stdint.h>

// Problem constants
#define Lc  4
#define Bc  8
#define Sc  1024
#define Dc  256
#define Hc  8
#define DHc 32
#define Ic  1024
#define Mc  4
#define TOK (Bc*Sc)          // 8192 tokens

// ---------------------------------------------------------------------------
// Scratch (no allocations allowed -> __device__ globals)
// ---------------------------------------------------------------------------
__device__ float g_h  [TOK*Dc];
__device__ float g_q  [TOK*Dc];
__device__ float g_k  [TOK*Dc];
__device__ float g_v  [TOK*Dc];
__device__ float g_ctx[TOK*Dc];
__device__ float g_tmp[TOK*Dc];
__device__ float g_ao [TOK*Dc];
__device__ float g_ff [TOK*Ic];

// ---------------------------------------------------------------------------
// Embedding + positional encoding: h[t,d] = emb[x[t],d] + pe[t%S, d]
// ---------------------------------------------------------------------------
__global__ void embed_kernel(const int* __restrict__ x,
                             const float* __restrict__ emb,
                             const float* __restrict__ pe)
{
    int gid = blockIdx.x * 256 + threadIdx.x;      // [0, TOK*Dc)
    int t = gid >> 8;
    int d = gid & 255;
    int tok = x[t];
    g_h[gid] = emb[tok * Dc + d] + pe[(t & (Sc - 1)) * Dc + d];
}

// ---------------------------------------------------------------------------
// Tiled SGEMM:  C[M,N] = A[M,K] @ W[N,K]^T + bias[N]  (torch Linear layout)
//   ep = 0: C = acc + bias
//   ep = 1: C = gelu_exact(acc + bias)
//   ep = 2: C = acc + bias + resid
// Tile: BM=128, BN=64, BK=16; 256 threads; 8x4 per thread.
// All dims divide evenly (M=8192, N in {256,1024}, K in {256,1024}).
// ---------------------------------------------------------------------------
#define GBM 128
#define GBN 64
#define GBK 16

__device__ __forceinline__ float gelu_exact(float v)
{
    return 0.5f * v * (1.0f + erff(v * 0.70710678118654752f));
}

__global__ __launch_bounds__(256)
void gemm_kernel(const float* __restrict__ A,
                 const float* __restrict__ W,
                 const float* __restrict__ bias,
                 const float* __restrict__ resid,
                 float* __restrict__ C,
                 int Ndim, int Kdim, int ep)
{
    __shared__ float As[GBK][GBM + 4];
    __shared__ float Bs[GBK][GBN + 4];

    const int tid  = threadIdx.x;
    const int row0 = blockIdx.y * GBM;
    const int col0 = blockIdx.x * GBN;
    const int tx   = tid & 15;   // N dir: 16 * 4 = 64
    const int ty   = tid >> 4;   // M dir: 16 * 8 = 128

    float acc[8][4];
#pragma unroll
    for (int i = 0; i < 8; i++)
#pragma unroll
        for (int j = 0; j < 4; j++) acc[i][j] = 0.f;

    for (int k0 = 0; k0 < Kdim; k0 += GBK) {
        // Load A tile (128x16 = 512 float4, 2 per thread), transposed into As[k][m]
#pragma unroll
        for (int i = 0; i < 2; i++) {
            int f  = tid + i * 256;
            int r  = f >> 2;
            int c4 = f & 3;
            float4 v = *(const float4*)(A + (size_t)(row0 + r) * Kdim + k0 + c4 * 4);
            As[c4 * 4 + 0][r] = v.x;
            As[c4 * 4 + 1][r] = v.y;
            As[c4 * 4 + 2][r] = v.z;
            As[c4 * 4 + 3][r] = v.w;
        }
        // Load B tile (64x16 = 256 float4, 1 per thread), transposed into Bs[k][n]
        {
            int r  = tid >> 2;
            int c4 = tid & 3;
            float4 v = *(const float4*)(W + (size_t)(col0 + r) * Kdim + k0 + c4 * 4);
            Bs[c4 * 4 + 0][r] = v.x;
            Bs[c4 * 4 + 1][r] = v.y;
            Bs[c4 * 4 + 2][r] = v.z;
            Bs[c4 * 4 + 3][r] = v.w;
        }
        __syncthreads();

#pragma unroll
        for (int k = 0; k < GBK; k++) {
            float a[8], bf[4];
            *(float4*)&a[0] = *(const float4*)&As[k][ty * 8];
            *(float4*)&a[4] = *(const float4*)&As[k][ty * 8 + 4];
            *(float4*)&bf[0] = *(const float4*)&Bs[k][tx * 4];
#pragma unroll
            for (int i = 0; i < 8; i++)
#pragma unroll
                for (int j = 0; j < 4; j++) acc[i][j] += a[i] * bf[j];
        }
        __syncthreads();
    }

    // Epilogue
    float4 bv = *(const float4*)(bias + col0 + tx * 4);
#pragma unroll
    for (int i = 0; i < 8; i++) {
        int r = row0 + ty * 8 + i;
        int c = col0 + tx * 4;
        float4 v;
        v.x = acc[i][0] + bv.x;
        v.y = acc[i][1] + bv.y;
        v.z = acc[i][2] + bv.z;
        v.w = acc[i][3] + bv.w;
        if (ep == 1) {
            v.x = gelu_exact(v.x); v.y = gelu_exact(v.y);
            v.z = gelu_exact(v.z); v.w = gelu_exact(v.w);
        } else if (ep == 2) {
            float4 rv = *(const float4*)(resid + (size_t)r * Ndim + c);
            v.x += rv.x; v.y += rv.y; v.z += rv.z; v.w += rv.w;
        }
        *(float4*)(C + (size_t)r * Ndim + c) = v;
    }
}

// ---------------------------------------------------------------------------
// Flash-style causal attention. grid = (S/128, B*H), block = 128.
// Thread = one query row; keys staged in 16-row smem tiles; online softmax.
// ---------------------------------------------------------------------------
__global__ __launch_bounds__(128)
void attn_kernel(const float* __restrict__ Q,
                 const float* __restrict__ Kp,
                 const float* __restrict__ Vp,
                 float* __restrict__ CTX)
{
    __shared__ float Ks[16][32];
    __shared__ float Vs[16][32];

    const int qt  = blockIdx.x;
    const int bh  = blockIdx.y;
    const int b   = bh >> 3;
    const int hh  = bh & 7;
    const int tid = threadIdx.x;
    const int qi  = qt * 128 + tid;

    const size_t qbase = ((size_t)(b * Sc + qi)) * Dc + hh * DHc;

    float qreg[32];
#pragma unroll
    for (int i = 0; i < 8; i++) {
        float4 t4 = *(const float4*)(Q + qbase + i * 4);
        qreg[i * 4 + 0] = t4.x; qreg[i * 4 + 1] = t4.y;
        qreg[i * 4 + 2] = t4.z; qreg[i * 4 + 3] = t4.w;
    }
    float acc[32];
#pragma unroll
    for (int d = 0; d < 32; d++) acc[d] = 0.f;

    float mx = -1e30f, l = 0.f;
    const float scale = 0.17677669529663689f;   // 1/sqrt(32)

    const int lr = tid >> 3;          // 0..15 (key row in tile)
    const int lc = (tid & 7) * 4;     // 0..28 (dh col, float4)
    const int kend = (qt + 1) * 128;

    for (int kt = 0; kt < kend; kt += 16) {
        const size_t kb = ((size_t)(b * Sc + kt + lr)) * Dc + hh * DHc + lc;
        __syncthreads();  // protect previous tile reads
        *(float4*)&Ks[lr][lc] = *(const float4*)(Kp + kb);
        *(float4*)&Vs[lr][lc] = *(const float4*)(Vp + kb);
        __syncthreads();

        float sv[16];
        float tmax = -1e30f;
#pragma unroll
        for (int kk = 0; kk < 16; kk++) {
            float dot = 0.f;
#pragma unroll
            for (int d4 = 0; d4 < 8; d4++) {
                float4 kv = *(const float4*)&Ks[kk][d4 * 4];
                dot += qreg[d4 * 4 + 0] * kv.x + qreg[d4 * 4 + 1] * kv.y
                     + qreg[d4 * 4 + 2] * kv.z + qreg[d4 * 4 + 3] * kv.w;
            }
            bool valid = (kt + kk) <= qi;
            float s = valid ? dot * scale : -1e30f;
            sv[kk] = s;
            tmax = fmaxf(tmax, s);
        }
        float mnew = fmaxf(mx, tmax);
        float corr = __expf(mx - mnew);   // exp(-1e30 - x) underflows to 0 cleanly
        mx = mnew;
        l *= corr;
#pragma unroll
        for (int d = 0; d < 32; d++) acc[d] *= corr;

#pragma unroll
        for (int kk = 0; kk < 16; kk++) {
            float p = (sv[kk] > -1e29f) ? __expf(sv[kk] - mnew) : 0.f;
            l += p;
#pragma unroll
            for (int d4 = 0; d4 < 8; d4++) {
                float4 vv = *(const float4*)&Vs[kk][d4 * 4];
                acc[d4 * 4 + 0] += p * vv.x;
                acc[d4 * 4 + 1] += p * vv.y;
                acc[d4 * 4 + 2] += p * vv.z;
                acc[d4 * 4 + 3] += p * vv.w;
            }
        }
    }

    const float inv = 1.f / l;
#pragma unroll
    for (int i = 0; i < 8; i++) {
        float4 o4 = make_float4(acc[i * 4 + 0] * inv, acc[i * 4 + 1] * inv,
                                acc[i * 4 + 2] * inv, acc[i * 4 + 3] * inv);
        *(float4*)(CTX + qbase + i * 4) = o4;
    }
}

// ---------------------------------------------------------------------------
// LayerNorm over last dim (256). One block (256 threads) per row. Two-pass.
// ---------------------------------------------------------------------------
__global__ __launch_bounds__(256)
void ln_kernel(const float* __restrict__ X,
               const float* __restrict__ gw,
               const float* __restrict__ bw,
               float* __restrict__ Y)
{
    const int row = blockIdx.x;
    const int d   = threadIdx.x;
    __shared__ float red[8];
    __shared__ float bc;

    float v = X[(size_t)row * Dc + d];

    // pass 1: mean
    float s = v;
#pragma unroll
    for (int o = 16; o > 0; o >>= 1) s += __shfl_down_sync(0xffffffffu, s, o);
    if ((d & 31) == 0) red[d >> 5] = s;
    __syncthreads();
    if (d == 0) {
        float t = 0.f;
#pragma unroll
        for (int i = 0; i < 8; i++) t += red[i];
        bc = t * (1.0f / Dc);
    }
    __syncthreads();
    const float m  = bc;
    const float dv = v - m;

    // pass 2: variance of (x - m)
    float s2 = dv * dv;
#pragma unroll
    for (int o = 16; o > 0; o >>= 1) s2 += __shfl_down_sync(0xffffffffu, s2, o);
    __syncthreads();                    // everyone has read bc; safe to reuse
    if ((d & 31) == 0) red[d >> 5] = s2;
    __syncthreads();
    if (d == 0) {
        float t = 0.f;
#pragma unroll
        for (int i = 0; i < 8; i++) t += red[i];
        bc = t * (1.0f / Dc);
    }
    __syncthreads();
    const float var = bc;

    Y[(size_t)row * Dc + d] = gw[d] * dv * rsqrtf(var + 1e-12f) + bw[d];
}

// ---------------------------------------------------------------------------
// Output projection: logits[t,m] = h[t,:] . out_w[m,:] + out_b[m]   (M=4)
// One warp per token; 8 warps per block.
// ---------------------------------------------------------------------------
__global__ __launch_bounds__(256)
void outproj_kernel(const float* __restrict__ ow,
                    const float* __restrict__ ob,
                    float* __restrict__ out)
{
    const int w    = threadIdx.x >> 5;
    const int lane = threadIdx.x & 31;
    const int t    = blockIdx.x * 8 + w;
    const float* hr = g_h + (size_t)t * Dc;

    float hv[8];
#pragma unroll
    for (int i = 0; i < 8; i++) hv[i] = hr[lane + 32 * i];

#pragma unroll
    for (int m = 0; m < Mc; m++) {
        const float* wr = ow + m * Dc;
        float p = 0.f;
#pragma unroll
        for (int i = 0; i < 8; i++) p += hv[i] * wr[lane + 32 * i];
#pragma unroll
        for (int o = 16; o > 0; o >>= 1) p += __shfl_down_sync(0xffffffffu, p, o);
        if (lane == 0) out[t * Mc + m] = p + ob[m];
    }
}

// ---------------------------------------------------------------------------
// Host orchestration (graph-capturable: kernel launches only)
// ---------------------------------------------------------------------------
extern "C" void kernel_launch(void* const* d_in, const int* in_sizes, int n_in,
                              void* d_out, int out_size)
{
    const int*   x     = (const int*)  d_in[0];
    const float* emb   = (const float*)d_in[1];
    const float* pe    = (const float*)d_in[2];
    const float* q_w   = (const float*)d_in[3];
    const float* q_b   = (const float*)d_in[4];
    const float* k_w   = (const float*)d_in[5];
    const float* k_b   = (const float*)d_in[6];
    const float* v_w   = (const float*)d_in[7];
    const float* v_b   = (const float*)d_in[8];
    const float* o_w   = (const float*)d_in[9];
    const float* o_b   = (const float*)d_in[10];
    const float* ln1_g = (const float*)d_in[11];
    const float* ln1_b = (const float*)d_in[12];
    const float* f1_w  = (const float*)d_in[13];
    const float* f1_b  = (const float*)d_in[14];
    const float* f2_w  = (const float*)d_in[15];
    const float* f2_b  = (const float*)d_in[16];
    const float* ln2_g = (const float*)d_in[17];
    const float* ln2_b = (const float*)d_in[18];
    const float* out_w = (const float*)d_in[19];
    const float* out_b = (const float*)d_in[20];
    float* out = (float*)d_out;

    float *h, *q, *k, *v, *ctx, *tmp, *ao, *ff;
    cudaGetSymbolAddress((void**)&h,   g_h);
    cudaGetSymbolAddress((void**)&q,   g_q);
    cudaGetSymbolAddress((void**)&k,   g_k);
    cudaGetSymbolAddress((void**)&v,   g_v);
    cudaGetSymbolAddress((void**)&ctx, g_ctx);
    cudaGetSymbolAddress((void**)&tmp, g_tmp);
    cudaGetSymbolAddress((void**)&ao,  g_ao);
    cudaGetSymbolAddress((void**)&ff,  g_ff);

    embed_kernel<<<TOK * Dc / 256, 256>>>(x, emb, pe);

    const dim3 gD(Dc / GBN, TOK / GBM);   // N=256 GEMMs:  (4, 64)
    const dim3 gI(Ic / GBN, TOK / GBM);   // N=1024 GEMM:  (16, 64)
    const dim3 gAttn(Sc / 128, Bc * Hc);  // (8, 64)

    for (int l = 0; l < Lc; l++) {
        const size_t wo  = (size_t)l * Dc * Dc;
        const size_t bo  = (size_t)l * Dc;
        const size_t f1o = (size_t)l * Ic * Dc;

        gemm_kernel<<<gD, 256>>>(h, q_w + wo, q_b + bo, nullptr, q, Dc, Dc, 0);
        gemm_kernel<<<gD, 256>>>(h, k_w + wo, k_b + bo, nullptr, k, Dc, Dc, 0);
        gemm_kernel<<<gD, 256>>>(h, v_w + wo, v_b + bo, nullptr, v, Dc, Dc, 0);

        attn_kernel<<<gAttn, 128>>>(q, k, v, ctx);

        // tmp = ctx @ o_w^T + o_b + h ; ao = LN1(tmp)
        gemm_kernel<<<gD, 256>>>(ctx, o_w + wo, o_b + bo, h, tmp, Dc, Dc, 2);
        ln_kernel<<<TOK, 256>>>(tmp, ln1_g + bo, ln1_b + bo, ao);

        // ff = gelu(ao @ f1^T + f1_b)
        gemm_kernel<<<gI, 256>>>(ao, f1_w + f1o, f1_b + (size_t)l * Ic, nullptr, ff, Ic, Dc, 1);
        // tmp = ff @ f2^T + f2_b + ao ; h = LN2(tmp)
        gemm_kernel<<<gD, 256>>>(ff, f2_w + f1o, f2_b + bo, ao, tmp, Dc, Ic, 2);
        ln_kernel<<<TOK, 256>>>(tmp, ln2_g + bo, ln2_b + bo, h);
    }

    outproj_kernel<<<TOK / 8, 256>>>(out_w, out_b, out);
}

// round 8
// speedup vs baseline: 1.0537x; 1.0537x over previous
#include <cuda_runtime.h>
#include <math.h>
#include <stdint.h>

// Problem constants
#define Lc  4
#define Bc  8
#define Sc  1024
#define Dc  256
#define Hc  8
#define DHc 32
#define Ic  1024
#define Mc  4
#define TOK (Bc*Sc)          // 8192 tokens

// ---------------------------------------------------------------------------
// Scratch (no allocations allowed -> __device__ globals)
// ---------------------------------------------------------------------------
__device__ float g_h  [TOK*Dc];
__device__ float g_q  [TOK*Dc];
__device__ float g_k  [TOK*Dc];
__device__ float g_v  [TOK*Dc];
__device__ float g_ctx[TOK*Dc];
__device__ float g_tmp[TOK*Dc];
__device__ float g_ao [TOK*Dc];
__device__ float g_ff [TOK*Ic];

// ---------------------------------------------------------------------------
// Embedding + positional encoding: h[t,d] = emb[x[t],d] + pe[t%S, d]
// ---------------------------------------------------------------------------
__global__ void embed_kernel(const int* __restrict__ x,
                             const float* __restrict__ emb,
                             const float* __restrict__ pe)
{
    int gid = blockIdx.x * 256 + threadIdx.x;      // [0, TOK*Dc)
    int t = gid >> 8;
    int d = gid & 255;
    int tok = x[t];
    g_h[gid] = emb[tok * Dc + d] + pe[(t & (Sc - 1)) * Dc + d];
}

// ---------------------------------------------------------------------------
// Tiled SGEMM:  C[M,N] = A[M,K] @ W[N,K]^T + bias[N]  (torch Linear layout)
//   ep = 0: C = acc + bias
//   ep = 1: C = gelu_exact(acc + bias)
//   ep = 2: C = acc + bias + resid
// Tile: BM=128, BN=64, BK=16; 256 threads; 8x4 per thread.
// All dims divide evenly (M=8192, N in {256,1024}, K in {256,1024}).
// ---------------------------------------------------------------------------
#define GBM 128
#define GBN 64
#define GBK 16

__device__ __forceinline__ float gelu_exact(float v)
{
    return 0.5f * v * (1.0f + erff(v * 0.70710678118654752f));
}

__global__ __launch_bounds__(256)
void gemm_kernel(const float* __restrict__ A,
                 const float* __restrict__ W,
                 const float* __restrict__ bias,
                 const float* __restrict__ resid,
                 float* __restrict__ C,
                 int Ndim, int Kdim, int ep)
{
    __shared__ float As[GBK][GBM + 4];
    __shared__ float Bs[GBK][GBN + 4];

    const int tid  = threadIdx.x;
    const int row0 = blockIdx.y * GBM;
    const int col0 = blockIdx.x * GBN;
    const int tx   = tid & 15;   // N dir: 16 * 4 = 64
    const int ty   = tid >> 4;   // M dir: 16 * 8 = 128

    float acc[8][4];
#pragma unroll
    for (int i = 0; i < 8; i++)
#pragma unroll
        for (int j = 0; j < 4; j++) acc[i][j] = 0.f;

    for (int k0 = 0; k0 < Kdim; k0 += GBK) {
        // Load A tile (128x16 = 512 float4, 2 per thread), transposed into As[k][m]
#pragma unroll
        for (int i = 0; i < 2; i++) {
            int f  = tid + i * 256;
            int r  = f >> 2;
            int c4 = f & 3;
            float4 v = *(const float4*)(A + (size_t)(row0 + r) * Kdim + k0 + c4 * 4);
            As[c4 * 4 + 0][r] = v.x;
            As[c4 * 4 + 1][r] = v.y;
            As[c4 * 4 + 2][r] = v.z;
            As[c4 * 4 + 3][r] = v.w;
        }
        // Load B tile (64x16 = 256 float4, 1 per thread), transposed into Bs[k][n]
        {
            int r  = tid >> 2;
            int c4 = tid & 3;
            float4 v = *(const float4*)(W + (size_t)(col0 + r) * Kdim + k0 + c4 * 4);
            Bs[c4 * 4 + 0][r] = v.x;
            Bs[c4 * 4 + 1][r] = v.y;
            Bs[c4 * 4 + 2][r] = v.z;
            Bs[c4 * 4 + 3][r] = v.w;
        }
        __syncthreads();

#pragma unroll
        for (int k = 0; k < GBK; k++) {
            float a[8], bf[4];
            *(float4*)&a[0] = *(const float4*)&As[k][ty * 8];
            *(float4*)&a[4] = *(const float4*)&As[k][ty * 8 + 4];
            *(float4*)&bf[0] = *(const float4*)&Bs[k][tx * 4];
#pragma unroll
            for (int i = 0; i < 8; i++)
#pragma unroll
                for (int j = 0; j < 4; j++) acc[i][j] += a[i] * bf[j];
        }
        __syncthreads();
    }

    // Epilogue
    float4 bv = *(const float4*)(bias + col0 + tx * 4);
#pragma unroll
    for (int i = 0; i < 8; i++) {
        int r = row0 + ty * 8 + i;
        int c = col0 + tx * 4;
        float4 v;
        v.x = acc[i][0] + bv.x;
        v.y = acc[i][1] + bv.y;
        v.z = acc[i][2] + bv.z;
        v.w = acc[i][3] + bv.w;
        if (ep == 1) {
            v.x = gelu_exact(v.x); v.y = gelu_exact(v.y);
            v.z = gelu_exact(v.z); v.w = gelu_exact(v.w);
        } else if (ep == 2) {
            float4 rv = *(const float4*)(resid + (size_t)r * Ndim + c);
            v.x += rv.x; v.y += rv.y; v.z += rv.z; v.w += rv.w;
        }
        *(float4*)(C + (size_t)r * Ndim + c) = v;
    }
}

// ---------------------------------------------------------------------------
// Flash-style causal attention. grid = (S/128, B*H), block = 128.
// Thread = one query row; keys staged in 16-row smem tiles; online softmax.
// ---------------------------------------------------------------------------
__global__ __launch_bounds__(128)
void attn_kernel(const float* __restrict__ Q,
                 const float* __restrict__ Kp,
                 const float* __restrict__ Vp,
                 float* __restrict__ CTX)
{
    __shared__ float Ks[16][32];
    __shared__ float Vs[16][32];

    const int qt  = blockIdx.x;
    const int bh  = blockIdx.y;
    const int b   = bh >> 3;
    const int hh  = bh & 7;
    const int tid = threadIdx.x;
    const int qi  = qt * 128 + tid;

    const size_t qbase = ((size_t)(b * Sc + qi)) * Dc + hh * DHc;

    float qreg[32];
#pragma unroll
    for (int i = 0; i < 8; i++) {
        float4 t4 = *(const float4*)(Q + qbase + i * 4);
        qreg[i * 4 + 0] = t4.x; qreg[i * 4 + 1] = t4.y;
        qreg[i * 4 + 2] = t4.z; qreg[i * 4 + 3] = t4.w;
    }
    float acc[32];
#pragma unroll
    for (int d = 0; d < 32; d++) acc[d] = 0.f;

    float mx = -1e30f, l = 0.f;
    const float scale = 0.17677669529663689f;   // 1/sqrt(32)

    const int lr = tid >> 3;          // 0..15 (key row in tile)
    const int lc = (tid & 7) * 4;     // 0..28 (dh col, float4)
    const int kend = (qt + 1) * 128;

    for (int kt = 0; kt < kend; kt += 16) {
        const size_t kb = ((size_t)(b * Sc + kt + lr)) * Dc + hh * DHc + lc;
        __syncthreads();  // protect previous tile reads
        *(float4*)&Ks[lr][lc] = *(const float4*)(Kp + kb);
        *(float4*)&Vs[lr][lc] = *(const float4*)(Vp + kb);
        __syncthreads();

        float sv[16];
        float tmax = -1e30f;
#pragma unroll
        for (int kk = 0; kk < 16; kk++) {
            float dot = 0.f;
#pragma unroll
            for (int d4 = 0; d4 < 8; d4++) {
                float4 kv = *(const float4*)&Ks[kk][d4 * 4];
                dot += qreg[d4 * 4 + 0] * kv.x + qreg[d4 * 4 + 1] * kv.y
                     + qreg[d4 * 4 + 2] * kv.z + qreg[d4 * 4 + 3] * kv.w;
            }
            bool valid = (kt + kk) <= qi;
            float s = valid ? dot * scale : -1e30f;
            sv[kk] = s;
            tmax = fmaxf(tmax, s);
        }
        float mnew = fmaxf(mx, tmax);
        float corr = __expf(mx - mnew);   // exp(-1e30 - x) underflows to 0 cleanly
        mx = mnew;
        l *= corr;
#pragma unroll
        for (int d = 0; d < 32; d++) acc[d] *= corr;

#pragma unroll
        for (int kk = 0; kk < 16; kk++) {
            float p = (sv[kk] > -1e29f) ? __expf(sv[kk] - mnew) : 0.f;
            l += p;
#pragma unroll
            for (int d4 = 0; d4 < 8; d4++) {
                float4 vv = *(const float4*)&Vs[kk][d4 * 4];
                acc[d4 * 4 + 0] += p * vv.x;
                acc[d4 * 4 + 1] += p * vv.y;
                acc[d4 * 4 + 2] += p * vv.z;
                acc[d4 * 4 + 3] += p * vv.w;
            }
        }
    }

    const float inv = 1.f / l;
#pragma unroll
    for (int i = 0; i < 8; i++) {
        float4 o4 = make_float4(acc[i * 4 + 0] * inv, acc[i * 4 + 1] * inv,
                                acc[i * 4 + 2] * inv, acc[i * 4 + 3] * inv);
        *(float4*)(CTX + qbase + i * 4) = o4;
    }
}

// ---------------------------------------------------------------------------
// LayerNorm over last dim (256). One block (256 threads) per row. Two-pass.
// ---------------------------------------------------------------------------
__global__ __launch_bounds__(256)
void ln_kernel(const float* __restrict__ X,
               const float* __restrict__ gw,
               const float* __restrict__ bw,
               float* __restrict__ Y)
{
    const int row = blockIdx.x;
    const int d   = threadIdx.x;
    __shared__ float red[8];
    __shared__ float bc;

    float v = X[(size_t)row * Dc + d];

    // pass 1: mean
    float s = v;
#pragma unroll
    for (int o = 16; o > 0; o >>= 1) s += __shfl_down_sync(0xffffffffu, s, o);
    if ((d & 31) == 0) red[d >> 5] = s;
    __syncthreads();
    if (d == 0) {
        float t = 0.f;
#pragma unroll
        for (int i = 0; i < 8; i++) t += red[i];
        bc = t * (1.0f / Dc);
    }
    __syncthreads();
    const float m  = bc;
    const float dv = v - m;

    // pass 2: variance of (x - m)
    float s2 = dv * dv;
#pragma unroll
    for (int o = 16; o > 0; o >>= 1) s2 += __shfl_down_sync(0xffffffffu, s2, o);
    __syncthreads();                    // everyone has read bc; safe to reuse
    if ((d & 31) == 0) red[d >> 5] = s2;
    __syncthreads();
    if (d == 0) {
        float t = 0.f;
#pragma unroll
        for (int i = 0; i < 8; i++) t += red[i];
        bc = t * (1.0f / Dc);
    }
    __syncthreads();
    const float var = bc;

    Y[(size_t)row * Dc + d] = gw[d] * dv * rsqrtf(var + 1e-12f) + bw[d];
}

// ---------------------------------------------------------------------------
// Output projection: logits[t,m] = h[t,:] . out_w[m,:] + out_b[m]   (M=4)
// One warp per token; 8 warps per block.
// ---------------------------------------------------------------------------
__global__ __launch_bounds__(256)
void outproj_kernel(const float* __restrict__ ow,
                    const float* __restrict__ ob,
                    float* __restrict__ out)
{
    const int w    = threadIdx.x >> 5;
    const int lane = threadIdx.x & 31;
    const int t    = blockIdx.x * 8 + w;
    const float* hr = g_h + (size_t)t * Dc;

    float hv[8];
#pragma unroll
    for (int i = 0; i < 8; i++) hv[i] = hr[lane + 32 * i];

#pragma unroll
    for (int m = 0; m < Mc; m++) {
        const float* wr = ow + m * Dc;
        float p = 0.f;
#pragma unroll
        for (int i = 0; i < 8; i++) p += hv[i] * wr[lane + 32 * i];
#pragma unroll
        for (int o = 16; o > 0; o >>= 1) p += __shfl_down_sync(0xffffffffu, p, o);
        if (lane == 0) out[t * Mc + m] = p + ob[m];
    }
}

// ---------------------------------------------------------------------------
// Host orchestration (graph-capturable: kernel launches only)
// ---------------------------------------------------------------------------
extern "C" void kernel_launch(void* const* d_in, const int* in_sizes, int n_in,
                              void* d_out, int out_size)
{
    const int*   x     = (const int*)  d_in[0];
    const float* emb   = (const float*)d_in[1];
    const float* pe    = (const float*)d_in[2];
    const float* q_w   = (const float*)d_in[3];
    const float* q_b   = (const float*)d_in[4];
    const float* k_w   = (const float*)d_in[5];
    const float* k_b   = (const float*)d_in[6];
    const float* v_w   = (const float*)d_in[7];
    const float* v_b   = (const float*)d_in[8];
    const float* o_w   = (const float*)d_in[9];
    const float* o_b   = (const float*)d_in[10];
    const float* ln1_g = (const float*)d_in[11];
    const float* ln1_b = (const float*)d_in[12];
    const float* f1_w  = (const float*)d_in[13];
    const float* f1_b  = (const float*)d_in[14];
    const float* f2_w  = (const float*)d_in[15];
    const float* f2_b  = (const float*)d_in[16];
    const float* ln2_g = (const float*)d_in[17];
    const float* ln2_b = (const float*)d_in[18];
    const float* out_w = (const float*)d_in[19];
    const float* out_b = (const float*)d_in[20];
    float* out = (float*)d_out;

    float *h, *q, *k, *v, *ctx, *tmp, *ao, *ff;
    cudaGetSymbolAddress((void**)&h,   g_h);
    cudaGetSymbolAddress((void**)&q,   g_q);
    cudaGetSymbolAddress((void**)&k,   g_k);
    cudaGetSymbolAddress((void**)&v,   g_v);
    cudaGetSymbolAddress((void**)&ctx, g_ctx);
    cudaGetSymbolAddress((void**)&tmp, g_tmp);
    cudaGetSymbolAddress((void**)&ao,  g_ao);
    cudaGetSymbolAddress((void**)&ff,  g_ff);

    embed_kernel<<<TOK * Dc / 256, 256>>>(x, emb, pe);

    const dim3 gD(Dc / GBN, TOK / GBM);   // N=256 GEMMs:  (4, 64)
    const dim3 gI(Ic / GBN, TOK / GBM);   // N=1024 GEMM:  (16, 64)
    const dim3 gAttn(Sc / 128, Bc * Hc);  // (8, 64)

    for (int l = 0; l < Lc; l++) {
        const size_t wo  = (size_t)l * Dc * Dc;
        const size_t bo  = (size_t)l * Dc;
        const size_t f1o = (size_t)l * Ic * Dc;

        gemm_kernel<<<gD, 256>>>(h, q_w + wo, q_b + bo, nullptr, q, Dc, Dc, 0);
        gemm_kernel<<<gD, 256>>>(h, k_w + wo, k_b + bo, nullptr, k, Dc, Dc, 0);
        gemm_kernel<<<gD, 256>>>(h, v_w + wo, v_b + bo, nullptr, v, Dc, Dc, 0);

        attn_kernel<<<gAttn, 128>>>(q, k, v, ctx);

        // tmp = ctx @ o_w^T + o_b + h ; ao = LN1(tmp)
        gemm_kernel<<<gD, 256>>>(ctx, o_w + wo, o_b + bo, h, tmp, Dc, Dc, 2);
        ln_kernel<<<TOK, 256>>>(tmp, ln1_g + bo, ln1_b + bo, ao);

        // ff = gelu(ao @ f1^T + f1_b)
        gemm_kernel<<<gI, 256>>>(ao, f1_w + f1o, f1_b + (size_t)l * Ic, nullptr, ff, Ic, Dc, 1);
        // tmp = ff @ f2^T + f2_b + ao ; h = LN2(tmp)
        gemm_kernel<<<gD, 256>>>(ff, f2_w + f1o, f2_b + bo, ao, tmp, Dc, Ic, 2);
        ln_kernel<<<TOK, 256>>>(tmp, ln2_g + bo, ln2_b + bo, h);
    }

    outproj_kernel<<<TOK / 8, 256>>>(out_w, out_b, out);
}